// round 1
// baseline (speedup 1.0000x reference)
#include <cuda_runtime.h>
#include <cstddef>

// Problem constants
#define BB   32
#define TT   2048
#define II   512
#define HH   512
#define MM   (BB * TT)          // 65536 GEMM rows
#define GSZ  ((size_t)MM * HH)  // elements per gate plane

// Scratch: pre-activations for 4 gates, [4][M][H] = 512 MB
__device__ float g_pre[4ull * MM * HH];

// ---------------------------------------------------------------------------
// GEMM: C_g[m][n] = sum_k x[m][k] * W_g[k][n]
// 128x128 tile, BK=8, 256 threads, 8x8 per-thread micro-tile.
// grid = (H/128=4, M/128=512, 4 gates)
// ---------------------------------------------------------------------------
#define Bb_M 128
#define Bb_N 128
#define Bb_K 8
#define T_M  8
#define T_N  8

__global__ __launch_bounds__(256, 2) void gemm_kernel(
    const float* __restrict__ A,
    const float* __restrict__ W0, const float* __restrict__ W1,
    const float* __restrict__ W2, const float* __restrict__ W3)
{
    const int K = II;
    const int N = HH;

    const int g = blockIdx.z;
    const float* Bp = (g == 0) ? W0 : (g == 1) ? W1 : (g == 2) ? W2 : W3;
    float* Cg = g_pre + (size_t)g * GSZ;

    __shared__ float As[Bb_K][Bb_M];
    __shared__ float Bs[Bb_K][Bb_N];

    const int tid  = threadIdx.x;
    const int brow = blockIdx.y;
    const int bcol = blockIdx.x;

    // A staging: one float4 per thread per K-step
    const int aRow  = tid >> 1;          // 0..127
    const int aCol4 = (tid & 1) * 4;     // 0 or 4
    // B staging: one float4 per thread per K-step
    const int bRow = tid >> 5;           // 0..7
    const int bCol = (tid & 31) * 4;     // 0..124

    const float* Aptr = A  + (size_t)(brow * Bb_M + aRow) * K + aCol4;
    const float* Bptr = Bp + (size_t)bRow * N + bcol * Bb_N + bCol;

    const int ty = tid >> 4;   // 0..15
    const int tx = tid & 15;   // 0..15

    float acc[T_M][T_N];
#pragma unroll
    for (int i = 0; i < T_M; i++)
#pragma unroll
        for (int j = 0; j < T_N; j++) acc[i][j] = 0.0f;

    for (int k0 = 0; k0 < K; k0 += Bb_K) {
        const float4 av = *(const float4*)Aptr;
        const float4 bv = *(const float4*)Bptr;
        As[aCol4 + 0][aRow] = av.x;
        As[aCol4 + 1][aRow] = av.y;
        As[aCol4 + 2][aRow] = av.z;
        As[aCol4 + 3][aRow] = av.w;
        *(float4*)&Bs[bRow][bCol] = bv;
        __syncthreads();

#pragma unroll
        for (int kk = 0; kk < Bb_K; kk++) {
            float4 a0 = *(const float4*)&As[kk][ty * T_M];
            float4 a1 = *(const float4*)&As[kk][ty * T_M + 4];
            float4 b0 = *(const float4*)&Bs[kk][tx * T_N];
            float4 b1 = *(const float4*)&Bs[kk][tx * T_N + 4];
            float ra[T_M] = {a0.x, a0.y, a0.z, a0.w, a1.x, a1.y, a1.z, a1.w};
            float rb[T_N] = {b0.x, b0.y, b0.z, b0.w, b1.x, b1.y, b1.z, b1.w};
#pragma unroll
            for (int i = 0; i < T_M; i++)
#pragma unroll
                for (int j = 0; j < T_N; j++)
                    acc[i][j] = fmaf(ra[i], rb[j], acc[i][j]);
        }
        __syncthreads();

        Aptr += Bb_K;
        Bptr += (size_t)Bb_K * N;
    }

    // Write back: rows brow*128 + ty*8 + i, cols bcol*128 + tx*8 + j
#pragma unroll
    for (int i = 0; i < T_M; i++) {
        float* Cp = Cg + (size_t)(brow * Bb_M + ty * T_M + i) * N + bcol * Bb_N + tx * T_N;
        *(float4*)(Cp)     = make_float4(acc[i][0], acc[i][1], acc[i][2], acc[i][3]);
        *(float4*)(Cp + 4) = make_float4(acc[i][4], acc[i][5], acc[i][6], acc[i][7]);
    }
}

// ---------------------------------------------------------------------------
// Scan: one thread per (b, h). Diagonal recurrence:
//   g_* = pre_* + h*u_* + b_* ; c = sig(g_f)*c + sig(g_i)*tanh(g_c)
//   h = sig(g_o)*tanh(c)
// Also zeroes the trailing h_t / c_t output sections.
// ---------------------------------------------------------------------------
__device__ __forceinline__ float sigmoidf_fast(float x) {
    return 1.0f / (1.0f + __expf(-x));
}

__global__ __launch_bounds__(128) void scan_kernel(
    const float* __restrict__ u_f, const float* __restrict__ b_f,
    const float* __restrict__ u_i, const float* __restrict__ b_i,
    const float* __restrict__ u_o, const float* __restrict__ b_o,
    const float* __restrict__ u_c, const float* __restrict__ b_c,
    float* __restrict__ out)
{
    const int idx = blockIdx.x * blockDim.x + threadIdx.x;  // 0..B*H-1
    if (idx >= BB * HH) return;
    const int b = idx / HH;
    const int h = idx % HH;

    const float uf = u_f[h], bf = b_f[h];
    const float ui = u_i[h], bi = b_i[h];
    const float uo = u_o[h], bo = b_o[h];
    const float uc = u_c[h], bc = b_c[h];

    const size_t base = (size_t)b * TT * HH + h;
    const float* __restrict__ pf = g_pre + 0 * GSZ + base;
    const float* __restrict__ pi = g_pre + 1 * GSZ + base;
    const float* __restrict__ po = g_pre + 2 * GSZ + base;
    const float* __restrict__ pc = g_pre + 3 * GSZ + base;
    float* __restrict__ ho = out + base;

    float hv = 0.0f, cv = 0.0f;

    for (int t = 0; t < TT; t++) {
        const size_t off = (size_t)t * HH;
        const float gf = pf[off] + fmaf(hv, uf, bf);
        const float gi = pi[off] + fmaf(hv, ui, bi);
        const float go = po[off] + fmaf(hv, uo, bo);
        const float gc = pc[off] + fmaf(hv, uc, bc);

        const float f_t = sigmoidf_fast(gf);
        const float i_t = sigmoidf_fast(gi);
        const float o_t = sigmoidf_fast(go);
        const float z_t = tanhf(gc);

        cv = fmaf(f_t, cv, i_t * z_t);
        hv = o_t * tanhf(cv);
        ho[off] = hv;
    }

    // Tail: h_t and c_t outputs are zeros ([1, B, H] each)
    out[(size_t)BB * TT * HH + idx]            = 0.0f;
    out[(size_t)BB * TT * HH + BB * HH + idx]  = 0.0f;
}

// ---------------------------------------------------------------------------
// Launch
// ---------------------------------------------------------------------------
extern "C" void kernel_launch(void* const* d_in, const int* in_sizes, int n_in,
                              void* d_out, int out_size)
{
    const float* x   = (const float*)d_in[0];
    const float* W_f = (const float*)d_in[1];
    const float* u_f = (const float*)d_in[2];
    const float* b_f = (const float*)d_in[3];
    const float* W_i = (const float*)d_in[4];
    const float* u_i = (const float*)d_in[5];
    const float* b_i = (const float*)d_in[6];
    const float* W_o = (const float*)d_in[7];
    const float* u_o = (const float*)d_in[8];
    const float* b_o = (const float*)d_in[9];
    const float* W_c = (const float*)d_in[10];
    const float* u_c = (const float*)d_in[11];
    const float* b_c = (const float*)d_in[12];
    float* out = (float*)d_out;

    dim3 ggrid(HH / Bb_N, MM / Bb_M, 4);   // (4, 512, 4)
    gemm_kernel<<<ggrid, 256>>>(x, W_f, W_i, W_o, W_c);

    const int nscan = BB * HH;             // 16384
    scan_kernel<<<(nscan + 127) / 128, 128>>>(u_f, b_f, u_i, b_i,
                                              u_o, b_o, u_c, b_c, out);
}

// round 5
// speedup vs baseline: 3.1068x; 3.1068x over previous
#include <cuda_runtime.h>
#include <cuda_bf16.h>
#include <cstdint>
#include <cstddef>

// ---------------------------------------------------------------------------
// Problem constants
// ---------------------------------------------------------------------------
#define BB 32
#define TT 2048
#define II 512
#define HH 512
#define MM (BB * TT)                 // 65536 GEMM rows
#define BH (BB * HH)                 // 16384
#define GSZ ((size_t)TT * BH)        // elems per gate plane

// Scratch (device globals; no runtime allocation allowed)
__device__ float          g_pre[4ull * GSZ];          // [gate][T][B*H], 512 MB
__device__ __nv_bfloat16  g_xhi[(size_t)MM * II];     // 64 MB
__device__ __nv_bfloat16  g_xlo[(size_t)MM * II];     // 64 MB
__device__ __nv_bfloat16  g_wth[4ull * HH * II];      // [g][n][k] = [2048][512]
__device__ __nv_bfloat16  g_wtl[4ull * HH * II];

// ---------------------------------------------------------------------------
// Helpers (base-ISA only: cp.async / ldmatrix / mma.sync all work at sm_103)
// ---------------------------------------------------------------------------
__device__ __forceinline__ uint32_t smem_u32(const void* p) {
    uint32_t a;
    asm("{ .reg .u64 t; cvta.to.shared.u64 t, %1; cvt.u32.u64 %0, t; }"
        : "=r"(a) : "l"(p));
    return a;
}

#define SWZ128(off) ((off) ^ (((off) >> 3) & 0x70))

__device__ __forceinline__ void cp_async16(uint32_t saddr, const void* gaddr) {
    asm volatile("cp.async.cg.shared.global [%0], [%1], 16;"
                 :: "r"(saddr), "l"(gaddr));
}
#define CP_COMMIT() asm volatile("cp.async.commit_group;" ::: "memory")
#define CP_WAIT(n)  asm volatile("cp.async.wait_group %0;" :: "n"(n) : "memory")

__device__ __forceinline__ void ldmatrix_x4(uint32_t& r0, uint32_t& r1,
                                            uint32_t& r2, uint32_t& r3,
                                            uint32_t addr) {
    asm volatile("ldmatrix.sync.aligned.m8n8.x4.shared.b16 {%0,%1,%2,%3}, [%4];"
                 : "=r"(r0), "=r"(r1), "=r"(r2), "=r"(r3) : "r"(addr));
}
__device__ __forceinline__ void ldmatrix_x2(uint32_t& r0, uint32_t& r1,
                                            uint32_t addr) {
    asm volatile("ldmatrix.sync.aligned.m8n8.x2.shared.b16 {%0,%1}, [%2];"
                 : "=r"(r0), "=r"(r1) : "r"(addr));
}

__device__ __forceinline__ void mma_bf16(float* c, const uint32_t* a,
                                         const uint32_t* b) {
    asm volatile(
        "mma.sync.aligned.m16n8k16.row.col.f32.bf16.bf16.f32 "
        "{%0,%1,%2,%3}, {%4,%5,%6,%7}, {%8,%9}, {%0,%1,%2,%3};"
        : "+f"(c[0]), "+f"(c[1]), "+f"(c[2]), "+f"(c[3])
        : "r"(a[0]), "r"(a[1]), "r"(a[2]), "r"(a[3]), "r"(b[0]), "r"(b[1]));
}

// ---------------------------------------------------------------------------
// Split-precision conversion kernels
// ---------------------------------------------------------------------------
__global__ __launch_bounds__(256) void convert_x_kernel(const float* __restrict__ x) {
    size_t i = ((size_t)blockIdx.x * 256 + threadIdx.x) * 4;
    float4 v = *(const float4*)(x + i);
    __nv_bfloat16 hx = __float2bfloat16(v.x);
    __nv_bfloat16 hy = __float2bfloat16(v.y);
    __nv_bfloat16 hz = __float2bfloat16(v.z);
    __nv_bfloat16 hw = __float2bfloat16(v.w);
    __nv_bfloat16 lx = __float2bfloat16(v.x - __bfloat162float(hx));
    __nv_bfloat16 ly = __float2bfloat16(v.y - __bfloat162float(hy));
    __nv_bfloat16 lz = __float2bfloat16(v.z - __bfloat162float(hz));
    __nv_bfloat16 lw = __float2bfloat16(v.w - __bfloat162float(hw));
    __nv_bfloat162* ph = (__nv_bfloat162*)(g_xhi + i);
    __nv_bfloat162* pl = (__nv_bfloat162*)(g_xlo + i);
    ph[0] = __nv_bfloat162(hx, hy); ph[1] = __nv_bfloat162(hz, hw);
    pl[0] = __nv_bfloat162(lx, ly); pl[1] = __nv_bfloat162(lz, lw);
}

__global__ __launch_bounds__(256) void convert_w_kernel(
    const float* __restrict__ Wf, const float* __restrict__ Wi,
    const float* __restrict__ Wo, const float* __restrict__ Wc)
{
    int idx = blockIdx.x * 256 + threadIdx.x;       // 0 .. 4*512*512-1
    int g = idx >> 18;
    int rem = idx & 262143;
    int n = rem >> 9;
    int k = rem & 511;
    const float* W = (g == 0) ? Wf : (g == 1) ? Wi : (g == 2) ? Wo : Wc;
    float v = W[k * HH + n];                        // transpose: [k][n] -> [n][k]
    __nv_bfloat16 h = __float2bfloat16(v);
    g_wth[idx] = h;
    g_wtl[idx] = __float2bfloat16(v - __bfloat162float(h));
}

// ---------------------------------------------------------------------------
// mma.sync GEMM: M=65536, N=2048 (4 gates x 512), K=512.
// CTA: 128x128, BK=64, 8 warps (2x4), warp tile 64x32, fp32 reg accum.
// D = x_hi*W_hi + x_hi*W_lo + x_lo*W_hi
// smem per stage: Ah/Al/Bh/Bl 16KB each = 64KB; 2 stages = 128KB.
// grid = (16 n-tiles, 512 m-tiles)
// ---------------------------------------------------------------------------
#define BKC     64
#define NKCH    (II / BKC)           // 8 chunks
#define TILE_B  16384                // bytes per operand tile (128 x 128B)
#define STAGE_B (4 * TILE_B)         // 64KB
#define AH_OFF  0
#define AL_OFF  TILE_B
#define BH_OFF  (2 * TILE_B)
#define BL_OFF  (3 * TILE_B)

__global__ __launch_bounds__(256, 1) void gemm_mma_kernel() {
    extern __shared__ char smem[];
    const uint32_t sb = smem_u32(smem);
    const int tid  = threadIdx.x;
    const int lane = tid & 31;
    const int warp = tid >> 5;
    const int wm = warp >> 2;           // 0..1 -> M offset wm*64
    const int wn = warp & 3;            // 0..3 -> N offset wn*32

    const int nt = blockIdx.x;          // 0..15
    const int my = blockIdx.y;          // 0..511

    const __nv_bfloat16* __restrict__ Ahg = g_xhi + (size_t)my * 128 * II;
    const __nv_bfloat16* __restrict__ Alg = g_xlo + (size_t)my * 128 * II;
    const __nv_bfloat16* __restrict__ Bhg = g_wth + (size_t)nt * 128 * II;
    const __nv_bfloat16* __restrict__ Blg = g_wtl + (size_t)nt * 128 * II;

    // loader: per chunk, each thread does 4 cp.async per tile (16 total)
    const int lrow = tid >> 1;                      // reused pattern
    (void)lrow;
    auto load_chunk = [&](int c, int s) {
        const uint32_t stg = sb + (uint32_t)s * STAGE_B;
        const int ko = c * BKC;
        #pragma unroll
        for (int i = 0; i < 4; i++) {
            const int u   = tid + i * 256;          // 0..1023
            const int row = u >> 3;
            const int un  = u & 7;
            const uint32_t so = SWZ128((uint32_t)(row * 128 + un * 16));
            const size_t  go = (size_t)row * II + ko + un * 8;
            cp_async16(stg + AH_OFF + so, Ahg + go);
            cp_async16(stg + AL_OFF + so, Alg + go);
            cp_async16(stg + BH_OFF + so, Bhg + go);
            cp_async16(stg + BL_OFF + so, Blg + go);
        }
        CP_COMMIT();
    };

    float acc[4][4][4];
    #pragma unroll
    for (int mi = 0; mi < 4; mi++)
        #pragma unroll
        for (int ni = 0; ni < 4; ni++)
            #pragma unroll
            for (int r = 0; r < 4; r++) acc[mi][ni][r] = 0.0f;

    // precomputed intra-tile ldmatrix offsets (swizzled, per kk added later)
    const int arow = (lane & 15);                   // fragment row
    const int akseg = (lane >> 4) << 4;             // 0 or 16 bytes
    const int brow = (lane & 7);
    const int bkseg = ((lane >> 3) & 1) << 4;

    load_chunk(0, 0);

    for (int c = 0; c < NKCH; c++) {
        const int s = c & 1;
        if (c + 1 < NKCH) { load_chunk(c + 1, (c + 1) & 1); CP_WAIT(1); }
        else              { CP_WAIT(0); }
        __syncthreads();

        const uint32_t stg = sb + (uint32_t)s * STAGE_B;
        #pragma unroll
        for (int kk = 0; kk < 4; kk++) {
            const int kb = kk * 32;                 // byte offset of 16-k group
            uint32_t ah[4][4], al[4][4], bh[4][2], bl[4][2];
            #pragma unroll
            for (int mi = 0; mi < 4; mi++) {
                const int r = wm * 64 + mi * 16 + arow;
                const uint32_t off = SWZ128((uint32_t)(r * 128 + kb + akseg));
                ldmatrix_x4(ah[mi][0], ah[mi][1], ah[mi][2], ah[mi][3],
                            stg + AH_OFF + off);
                ldmatrix_x4(al[mi][0], al[mi][1], al[mi][2], al[mi][3],
                            stg + AL_OFF + off);
            }
            #pragma unroll
            for (int ni = 0; ni < 4; ni++) {
                const int r = wn * 32 + ni * 8 + brow;
                const uint32_t off = SWZ128((uint32_t)(r * 128 + kb + bkseg));
                ldmatrix_x2(bh[ni][0], bh[ni][1], stg + BH_OFF + off);
                ldmatrix_x2(bl[ni][0], bl[ni][1], stg + BL_OFF + off);
            }
            #pragma unroll
            for (int mi = 0; mi < 4; mi++)
                #pragma unroll
                for (int ni = 0; ni < 4; ni++) {
                    mma_bf16(acc[mi][ni], ah[mi], bh[ni]);
                    mma_bf16(acc[mi][ni], ah[mi], bl[ni]);
                    mma_bf16(acc[mi][ni], al[mi], bh[ni]);
                }
        }
        __syncthreads();
    }

    // ---- epilogue: direct time-major stores
    // m = my*128 + r  ->  b_ = my>>4, t = (my&15)*128 + r
    // n = nt*128 + cl ->  g = nt>>2, h = (nt&3)*128 + cl
    const int b_ = my >> 4;
    const int t0 = (my & 15) << 7;
    const int g  = nt >> 2;
    const int h0 = (nt & 3) << 7;
    float* plane = g_pre + (size_t)g * GSZ + (size_t)t0 * BH + b_ * HH + h0;

    #pragma unroll
    for (int mi = 0; mi < 4; mi++) {
        const int r0 = wm * 64 + mi * 16 + (lane >> 2);
        #pragma unroll
        for (int ni = 0; ni < 4; ni++) {
            const int cl = wn * 32 + ni * 8 + (lane & 3) * 2;
            float* p0 = plane + (size_t)r0 * BH + cl;
            float* p1 = p0 + (size_t)8 * BH;
            *(float2*)p0 = make_float2(acc[mi][ni][0], acc[mi][ni][1]);
            *(float2*)p1 = make_float2(acc[mi][ni][2], acc[mi][ni][3]);
        }
    }
}

// ---------------------------------------------------------------------------
// Scan: one thread per (b,h); 8-step register double buffer.
// pre layout: [gate][t][b*H + h]
// ---------------------------------------------------------------------------
__device__ __forceinline__ float sigf(float x) {
    return 1.0f / (1.0f + __expf(-x));
}

__global__ __launch_bounds__(128) void scan_kernel(
    const float* __restrict__ u_f, const float* __restrict__ b_f,
    const float* __restrict__ u_i, const float* __restrict__ b_i,
    const float* __restrict__ u_o, const float* __restrict__ b_o,
    const float* __restrict__ u_c, const float* __restrict__ b_c,
    float* __restrict__ out)
{
    const int idx = blockIdx.x * 128 + threadIdx.x;   // 0..BH-1
    const int b = idx >> 9;
    const int h = idx & 511;

    const float uf = u_f[h], bf = b_f[h];
    const float ui = u_i[h], bi = b_i[h];
    const float uo = u_o[h], bo = b_o[h];
    const float uc = u_c[h], bc = b_c[h];

    const float* __restrict__ p0 = g_pre + 0 * GSZ + idx;
    const float* __restrict__ p1 = g_pre + 1 * GSZ + idx;
    const float* __restrict__ p2 = g_pre + 2 * GSZ + idx;
    const float* __restrict__ p3 = g_pre + 3 * GSZ + idx;
    float* __restrict__ ho = out + (size_t)b * TT * HH + h;

    float cur[8][4], nxt[8][4];
    #pragma unroll
    for (int j = 0; j < 8; j++) {
        const size_t o = (size_t)j * BH;
        cur[j][0] = p0[o]; cur[j][1] = p1[o];
        cur[j][2] = p2[o]; cur[j][3] = p3[o];
    }

    float hv = 0.0f, cv = 0.0f;
    for (int tb = 0; tb < TT; tb += 8) {
        const int tn = tb + 8;
        if (tn < TT) {
            #pragma unroll
            for (int j = 0; j < 8; j++) {
                const size_t o = (size_t)(tn + j) * BH;
                nxt[j][0] = p0[o]; nxt[j][1] = p1[o];
                nxt[j][2] = p2[o]; nxt[j][3] = p3[o];
            }
        }
        #pragma unroll
        for (int j = 0; j < 8; j++) {
            const float gf = cur[j][0] + fmaf(hv, uf, bf);
            const float gi = cur[j][1] + fmaf(hv, ui, bi);
            const float go = cur[j][2] + fmaf(hv, uo, bo);
            const float gc = cur[j][3] + fmaf(hv, uc, bc);
            cv = fmaf(sigf(gf), cv, sigf(gi) * tanhf(gc));
            hv = sigf(go) * tanhf(cv);
            ho[(size_t)(tb + j) * HH] = hv;
        }
        #pragma unroll
        for (int j = 0; j < 8; j++) {
            cur[j][0] = nxt[j][0]; cur[j][1] = nxt[j][1];
            cur[j][2] = nxt[j][2]; cur[j][3] = nxt[j][3];
        }
    }

    // h_t / c_t tails are zeros
    out[(size_t)BB * TT * HH + idx]      = 0.0f;
    out[(size_t)BB * TT * HH + BH + idx] = 0.0f;
}

// ---------------------------------------------------------------------------
// Launch
// ---------------------------------------------------------------------------
extern "C" void kernel_launch(void* const* d_in, const int* in_sizes, int n_in,
                              void* d_out, int out_size)
{
    const float* x   = (const float*)d_in[0];
    const float* W_f = (const float*)d_in[1];
    const float* u_f = (const float*)d_in[2];
    const float* b_f = (const float*)d_in[3];
    const float* W_i = (const float*)d_in[4];
    const float* u_i = (const float*)d_in[5];
    const float* b_i = (const float*)d_in[6];
    const float* W_o = (const float*)d_in[7];
    const float* u_o = (const float*)d_in[8];
    const float* b_o = (const float*)d_in[9];
    const float* W_c = (const float*)d_in[10];
    const float* u_c = (const float*)d_in[11];
    const float* b_c = (const float*)d_in[12];
    float* out = (float*)d_out;

    static int smem_set = 0;
    if (!smem_set) {
        cudaFuncSetAttribute(gemm_mma_kernel,
                             cudaFuncAttributeMaxDynamicSharedMemorySize,
                             2 * STAGE_B);
        smem_set = 1;
    }

    convert_x_kernel<<<(int)((size_t)MM * II / (256 * 4)), 256>>>(x);
    convert_w_kernel<<<4 * II * HH / 256, 256>>>(W_f, W_i, W_o, W_c);

    dim3 ggrid(16, 512);
    gemm_mma_kernel<<<ggrid, 256, 2 * STAGE_B>>>();

    scan_kernel<<<BH / 128, 128>>>(u_f, b_f, u_i, b_i,
                                   u_o, b_o, u_c, b_c, out);
}

// round 10
// speedup vs baseline: 3.3006x; 1.0624x over previous
#include <cuda_runtime.h>
#include <cuda_bf16.h>
#include <cstdint>
#include <cstddef>

// ---------------------------------------------------------------------------
// Problem constants
// ---------------------------------------------------------------------------
#define BB 32
#define TT 2048
#define II 512
#define HH 512
#define MM (BB * TT)                 // 65536 GEMM rows
#define BH (BB * HH)                 // 16384
#define GSZ ((size_t)TT * BH)        // elems per gate plane

// Scratch (device globals; no runtime allocation allowed)
__device__ float          g_pre[4ull * GSZ];          // [gate][T][B*H], 512 MB
__device__ __nv_bfloat16  g_xhi[(size_t)MM * II];     // 64 MB
__device__ __nv_bfloat16  g_xlo[(size_t)MM * II];     // 64 MB
__device__ __nv_bfloat16  g_wth[4ull * HH * II];      // [g][n][k] = [2048][512]
__device__ __nv_bfloat16  g_wtl[4ull * HH * II];

// ---------------------------------------------------------------------------
// Helpers (base-ISA only: cp.async / ldmatrix / mma.sync all work at sm_103)
// ---------------------------------------------------------------------------
__device__ __forceinline__ uint32_t smem_u32(const void* p) {
    uint32_t a;
    asm("{ .reg .u64 t; cvta.to.shared.u64 t, %1; cvt.u32.u64 %0, t; }"
        : "=r"(a) : "l"(p));
    return a;
}

#define SWZ128(off) ((off) ^ (((off) >> 3) & 0x70))

__device__ __forceinline__ void cp_async16(uint32_t saddr, const void* gaddr) {
    asm volatile("cp.async.cg.shared.global [%0], [%1], 16;"
                 :: "r"(saddr), "l"(gaddr));
}
#define CP_COMMIT() asm volatile("cp.async.commit_group;" ::: "memory")
#define CP_WAIT(n)  asm volatile("cp.async.wait_group %0;" :: "n"(n) : "memory")

__device__ __forceinline__ void ldmatrix_x4(uint32_t& r0, uint32_t& r1,
                                            uint32_t& r2, uint32_t& r3,
                                            uint32_t addr) {
    asm volatile("ldmatrix.sync.aligned.m8n8.x4.shared.b16 {%0,%1,%2,%3}, [%4];"
                 : "=r"(r0), "=r"(r1), "=r"(r2), "=r"(r3) : "r"(addr));
}
__device__ __forceinline__ void ldmatrix_x2(uint32_t& r0, uint32_t& r1,
                                            uint32_t addr) {
    asm volatile("ldmatrix.sync.aligned.m8n8.x2.shared.b16 {%0,%1}, [%2];"
                 : "=r"(r0), "=r"(r1) : "r"(addr));
}

__device__ __forceinline__ void mma_bf16(float* c, const uint32_t* a,
                                         const uint32_t* b) {
    asm volatile(
        "mma.sync.aligned.m16n8k16.row.col.f32.bf16.bf16.f32 "
        "{%0,%1,%2,%3}, {%4,%5,%6,%7}, {%8,%9}, {%0,%1,%2,%3};"
        : "+f"(c[0]), "+f"(c[1]), "+f"(c[2]), "+f"(c[3])
        : "r"(a[0]), "r"(a[1]), "r"(a[2]), "r"(a[3]), "r"(b[0]), "r"(b[1]));
}

// ---------------------------------------------------------------------------
// Split-precision conversion kernels
// ---------------------------------------------------------------------------
__global__ __launch_bounds__(256) void convert_x_kernel(const float* __restrict__ x) {
    size_t i = ((size_t)blockIdx.x * 256 + threadIdx.x) * 4;
    float4 v = *(const float4*)(x + i);
    __nv_bfloat16 hx = __float2bfloat16(v.x);
    __nv_bfloat16 hy = __float2bfloat16(v.y);
    __nv_bfloat16 hz = __float2bfloat16(v.z);
    __nv_bfloat16 hw = __float2bfloat16(v.w);
    __nv_bfloat16 lx = __float2bfloat16(v.x - __bfloat162float(hx));
    __nv_bfloat16 ly = __float2bfloat16(v.y - __bfloat162float(hy));
    __nv_bfloat16 lz = __float2bfloat16(v.z - __bfloat162float(hz));
    __nv_bfloat16 lw = __float2bfloat16(v.w - __bfloat162float(hw));
    __nv_bfloat162* ph = (__nv_bfloat162*)(g_xhi + i);
    __nv_bfloat162* pl = (__nv_bfloat162*)(g_xlo + i);
    ph[0] = __nv_bfloat162(hx, hy); ph[1] = __nv_bfloat162(hz, hw);
    pl[0] = __nv_bfloat162(lx, ly); pl[1] = __nv_bfloat162(lz, lw);
}

__global__ __launch_bounds__(256) void convert_w_kernel(
    const float* __restrict__ Wf, const float* __restrict__ Wi,
    const float* __restrict__ Wo, const float* __restrict__ Wc)
{
    int idx = blockIdx.x * 256 + threadIdx.x;       // 0 .. 4*512*512-1
    int g = idx >> 18;
    int rem = idx & 262143;
    int n = rem >> 9;
    int k = rem & 511;
    const float* W = (g == 0) ? Wf : (g == 1) ? Wi : (g == 2) ? Wo : Wc;
    float v = W[k * HH + n];                        // transpose: [k][n] -> [n][k]
    __nv_bfloat16 h = __float2bfloat16(v);
    g_wth[idx] = h;
    g_wtl[idx] = __float2bfloat16(v - __bfloat162float(h));
}

// ---------------------------------------------------------------------------
// mma.sync GEMM: M=65536, N=2048 (4 gates x 512), K=512.
// CTA: 128x128, BK=64, 8 warps (2x4), warp tile 64x32, fp32 reg accum.
// D = x_hi*W_hi + x_hi*W_lo + x_lo*W_hi
// smem per stage: Ah/Al/Bh/Bl 16KB each = 64KB; 2 stages = 128KB.
// grid = (16 n-tiles, 512 m-tiles)
// ---------------------------------------------------------------------------
#define BKC     64
#define NKCH    (II / BKC)           // 8 chunks
#define TILE_B  16384                // bytes per operand tile (128 x 128B)
#define STAGE_B (4 * TILE_B)         // 64KB
#define AH_OFF  0
#define AL_OFF  TILE_B
#define BH_OFF  (2 * TILE_B)
#define BL_OFF  (3 * TILE_B)

__global__ __launch_bounds__(256, 1) void gemm_mma_kernel() {
    extern __shared__ char smem[];
    const uint32_t sb = smem_u32(smem);
    const int tid  = threadIdx.x;
    const int lane = tid & 31;
    const int warp = tid >> 5;
    const int wm = warp >> 2;           // 0..1 -> M offset wm*64
    const int wn = warp & 3;            // 0..3 -> N offset wn*32

    const int nt = blockIdx.x;          // 0..15
    const int my = blockIdx.y;          // 0..511

    const __nv_bfloat16* __restrict__ Ahg = g_xhi + (size_t)my * 128 * II;
    const __nv_bfloat16* __restrict__ Alg = g_xlo + (size_t)my * 128 * II;
    const __nv_bfloat16* __restrict__ Bhg = g_wth + (size_t)nt * 128 * II;
    const __nv_bfloat16* __restrict__ Blg = g_wtl + (size_t)nt * 128 * II;

    auto load_chunk = [&](int c, int s) {
        const uint32_t stg = sb + (uint32_t)s * STAGE_B;
        const int ko = c * BKC;
        #pragma unroll
        for (int i = 0; i < 4; i++) {
            const int u   = tid + i * 256;          // 0..1023
            const int row = u >> 3;
            const int un  = u & 7;
            const uint32_t so = SWZ128((uint32_t)(row * 128 + un * 16));
            const size_t  go = (size_t)row * II + ko + un * 8;
            cp_async16(stg + AH_OFF + so, Ahg + go);
            cp_async16(stg + AL_OFF + so, Alg + go);
            cp_async16(stg + BH_OFF + so, Bhg + go);
            cp_async16(stg + BL_OFF + so, Blg + go);
        }
        CP_COMMIT();
    };

    float acc[4][4][4];
    #pragma unroll
    for (int mi = 0; mi < 4; mi++)
        #pragma unroll
        for (int ni = 0; ni < 4; ni++)
            #pragma unroll
            for (int r = 0; r < 4; r++) acc[mi][ni][r] = 0.0f;

    const int arow = (lane & 15);                   // fragment row
    const int akseg = (lane >> 4) << 4;             // 0 or 16 bytes
    const int brow = (lane & 7);
    const int bkseg = ((lane >> 3) & 1) << 4;

    load_chunk(0, 0);

    for (int c = 0; c < NKCH; c++) {
        const int s = c & 1;
        if (c + 1 < NKCH) { load_chunk(c + 1, (c + 1) & 1); CP_WAIT(1); }
        else              { CP_WAIT(0); }
        __syncthreads();

        const uint32_t stg = sb + (uint32_t)s * STAGE_B;
        #pragma unroll
        for (int kk = 0; kk < 4; kk++) {
            const int kb = kk * 32;                 // byte offset of 16-k group
            uint32_t ah[4][4], al[4][4], bh[4][2], bl[4][2];
            #pragma unroll
            for (int mi = 0; mi < 4; mi++) {
                const int r = wm * 64 + mi * 16 + arow;
                const uint32_t off = SWZ128((uint32_t)(r * 128 + kb + akseg));
                ldmatrix_x4(ah[mi][0], ah[mi][1], ah[mi][2], ah[mi][3],
                            stg + AH_OFF + off);
                ldmatrix_x4(al[mi][0], al[mi][1], al[mi][2], al[mi][3],
                            stg + AL_OFF + off);
            }
            #pragma unroll
            for (int ni = 0; ni < 4; ni++) {
                const int r = wn * 32 + ni * 8 + brow;
                const uint32_t off = SWZ128((uint32_t)(r * 128 + kb + bkseg));
                ldmatrix_x2(bh[ni][0], bh[ni][1], stg + BH_OFF + off);
                ldmatrix_x2(bl[ni][0], bl[ni][1], stg + BL_OFF + off);
            }
            #pragma unroll
            for (int mi = 0; mi < 4; mi++)
                #pragma unroll
                for (int ni = 0; ni < 4; ni++) {
                    mma_bf16(acc[mi][ni], ah[mi], bh[ni]);
                    mma_bf16(acc[mi][ni], ah[mi], bl[ni]);
                    mma_bf16(acc[mi][ni], al[mi], bh[ni]);
                }
        }
        __syncthreads();
    }

    // ---- epilogue: direct time-major stores
    const int b_ = my >> 4;
    const int t0 = (my & 15) << 7;
    const int g  = nt >> 2;
    const int h0 = (nt & 3) << 7;
    float* plane = g_pre + (size_t)g * GSZ + (size_t)t0 * BH + b_ * HH + h0;

    #pragma unroll
    for (int mi = 0; mi < 4; mi++) {
        const int r0 = wm * 64 + mi * 16 + (lane >> 2);
        #pragma unroll
        for (int ni = 0; ni < 4; ni++) {
            const int cl = wn * 32 + ni * 8 + (lane & 3) * 2;
            float* p0 = plane + (size_t)r0 * BH + cl;
            float* p1 = p0 + (size_t)8 * BH;
            *(float2*)p0 = make_float2(acc[mi][ni][0], acc[mi][ni][1]);
            *(float2*)p1 = make_float2(acc[mi][ni][2], acc[mi][ni][3]);
        }
    }
}

// ---------------------------------------------------------------------------
// Scan: one thread per (b,h); 8-step register double buffer.
// Fast MUFU-based activations: sigma via ex2+rcp, tanh(x) = 2*sigma(2x)-1
// (saturates correctly under exp overflow/underflow).
// pre layout: [gate][t][b*H + h]
// ---------------------------------------------------------------------------
__device__ __forceinline__ float sigf(float x) {
    return __fdividef(1.0f, 1.0f + __expf(-x));
}
__device__ __forceinline__ float ftanh(float x) {
    return __fmaf_rn(2.0f, sigf(2.0f * x), -1.0f);
}

#define SCAN_THREADS 64

__global__ __launch_bounds__(SCAN_THREADS) void scan_kernel(
    const float* __restrict__ u_f, const float* __restrict__ b_f,
    const float* __restrict__ u_i, const float* __restrict__ b_i,
    const float* __restrict__ u_o, const float* __restrict__ b_o,
    const float* __restrict__ u_c, const float* __restrict__ b_c,
    float* __restrict__ out)
{
    const int idx = blockIdx.x * SCAN_THREADS + threadIdx.x;   // 0..BH-1
    const int b = idx >> 9;
    const int h = idx & 511;

    const float uf = u_f[h], bf = b_f[h];
    const float ui = u_i[h], bi = b_i[h];
    const float uo = u_o[h], bo = b_o[h];
    const float uc = u_c[h], bc = b_c[h];

    const float* __restrict__ p0 = g_pre + 0 * GSZ + idx;
    const float* __restrict__ p1 = g_pre + 1 * GSZ + idx;
    const float* __restrict__ p2 = g_pre + 2 * GSZ + idx;
    const float* __restrict__ p3 = g_pre + 3 * GSZ + idx;
    float* __restrict__ ho = out + (size_t)b * TT * HH + h;

    float cur[8][4], nxt[8][4];
    #pragma unroll
    for (int j = 0; j < 8; j++) {
        const size_t o = (size_t)j * BH;
        cur[j][0] = p0[o]; cur[j][1] = p1[o];
        cur[j][2] = p2[o]; cur[j][3] = p3[o];
    }

    float hv = 0.0f, cv = 0.0f;
    for (int tb = 0; tb < TT; tb += 8) {
        const int tn = tb + 8;
        if (tn < TT) {
            #pragma unroll
            for (int j = 0; j < 8; j++) {
                const size_t o = (size_t)(tn + j) * BH;
                nxt[j][0] = p0[o]; nxt[j][1] = p1[o];
                nxt[j][2] = p2[o]; nxt[j][3] = p3[o];
            }
        }
        #pragma unroll
        for (int j = 0; j < 8; j++) {
            const float gf = cur[j][0] + fmaf(hv, uf, bf);
            const float gi = cur[j][1] + fmaf(hv, ui, bi);
            const float go = cur[j][2] + fmaf(hv, uo, bo);
            const float gc = cur[j][3] + fmaf(hv, uc, bc);
            cv = fmaf(sigf(gf), cv, sigf(gi) * ftanh(gc));
            hv = sigf(go) * ftanh(cv);
            ho[(size_t)(tb + j) * HH] = hv;
        }
        #pragma unroll
        for (int j = 0; j < 8; j++) {
            cur[j][0] = nxt[j][0]; cur[j][1] = nxt[j][1];
            cur[j][2] = nxt[j][2]; cur[j][3] = nxt[j][3];
        }
    }

    // h_t / c_t tails are zeros
    out[(size_t)BB * TT * HH + idx]      = 0.0f;
    out[(size_t)BB * TT * HH + BH + idx] = 0.0f;
}

// ---------------------------------------------------------------------------
// Launch
// ---------------------------------------------------------------------------
extern "C" void kernel_launch(void* const* d_in, const int* in_sizes, int n_in,
                              void* d_out, int out_size)
{
    const float* x   = (const float*)d_in[0];
    const float* W_f = (const float*)d_in[1];
    const float* u_f = (const float*)d_in[2];
    const float* b_f = (const float*)d_in[3];
    const float* W_i = (const float*)d_in[4];
    const float* u_i = (const float*)d_in[5];
    const float* b_i = (const float*)d_in[6];
    const float* W_o = (const float*)d_in[7];
    const float* u_o = (const float*)d_in[8];
    const float* b_o = (const float*)d_in[9];
    const float* W_c = (const float*)d_in[10];
    const float* u_c = (const float*)d_in[11];
    const float* b_c = (const float*)d_in[12];
    float* out = (float*)d_out;

    static int smem_set = 0;
    if (!smem_set) {
        cudaFuncSetAttribute(gemm_mma_kernel,
                             cudaFuncAttributeMaxDynamicSharedMemorySize,
                             2 * STAGE_B);
        smem_set = 1;
    }

    convert_x_kernel<<<(int)((size_t)MM * II / (256 * 4)), 256>>>(x);
    convert_w_kernel<<<4 * II * HH / 256, 256>>>(W_f, W_i, W_o, W_c);

    dim3 ggrid(16, 512);
    gemm_mma_kernel<<<ggrid, 256, 2 * STAGE_B>>>();

    scan_kernel<<<BH / SCAN_THREADS, SCAN_THREADS>>>(u_f, b_f, u_i, b_i,
                                                     u_o, b_o, u_c, b_c, out);
}

// round 11
// speedup vs baseline: 3.3726x; 1.0218x over previous
#include <cuda_runtime.h>
#include <cuda_bf16.h>
#include <cstdint>
#include <cstddef>

// ---------------------------------------------------------------------------
// Problem constants
// ---------------------------------------------------------------------------
#define BB 32
#define TT 2048
#define II 512
#define HH 512
#define MM (BB * TT)                 // 65536 GEMM rows
#define BH (BB * HH)                 // 16384
#define GSZ ((size_t)TT * BH)        // elems per gate plane

// Scratch (device globals; no runtime allocation allowed)
// g_pre layout: [t][b*H + h][4 gates]  (gate-interleaved, 512 MB)
__device__ float          g_pre[4ull * GSZ];
__device__ __nv_bfloat16  g_xhi[(size_t)MM * II];     // 64 MB
__device__ __nv_bfloat16  g_xlo[(size_t)MM * II];     // 64 MB
// W transposed + gate-interleaved: row n' = h*4 + g, col k. [2048][512]
__device__ __nv_bfloat16  g_wth[4ull * HH * II];
__device__ __nv_bfloat16  g_wtl[4ull * HH * II];

// ---------------------------------------------------------------------------
// Helpers (base-ISA only: cp.async / ldmatrix / mma.sync all work at sm_103)
// ---------------------------------------------------------------------------
__device__ __forceinline__ uint32_t smem_u32(const void* p) {
    uint32_t a;
    asm("{ .reg .u64 t; cvta.to.shared.u64 t, %1; cvt.u32.u64 %0, t; }"
        : "=r"(a) : "l"(p));
    return a;
}

#define SWZ128(off) ((off) ^ (((off) >> 3) & 0x70))

__device__ __forceinline__ void cp_async16(uint32_t saddr, const void* gaddr) {
    asm volatile("cp.async.cg.shared.global [%0], [%1], 16;"
                 :: "r"(saddr), "l"(gaddr));
}
#define CP_COMMIT() asm volatile("cp.async.commit_group;" ::: "memory")
#define CP_WAIT(n)  asm volatile("cp.async.wait_group %0;" :: "n"(n) : "memory")

__device__ __forceinline__ void ldmatrix_x4(uint32_t& r0, uint32_t& r1,
                                            uint32_t& r2, uint32_t& r3,
                                            uint32_t addr) {
    asm volatile("ldmatrix.sync.aligned.m8n8.x4.shared.b16 {%0,%1,%2,%3}, [%4];"
                 : "=r"(r0), "=r"(r1), "=r"(r2), "=r"(r3) : "r"(addr));
}
__device__ __forceinline__ void ldmatrix_x2(uint32_t& r0, uint32_t& r1,
                                            uint32_t addr) {
    asm volatile("ldmatrix.sync.aligned.m8n8.x2.shared.b16 {%0,%1}, [%2];"
                 : "=r"(r0), "=r"(r1) : "r"(addr));
}

__device__ __forceinline__ void mma_bf16(float* c, const uint32_t* a,
                                         const uint32_t* b) {
    asm volatile(
        "mma.sync.aligned.m16n8k16.row.col.f32.bf16.bf16.f32 "
        "{%0,%1,%2,%3}, {%4,%5,%6,%7}, {%8,%9}, {%0,%1,%2,%3};"
        : "+f"(c[0]), "+f"(c[1]), "+f"(c[2]), "+f"(c[3])
        : "r"(a[0]), "r"(a[1]), "r"(a[2]), "r"(a[3]), "r"(b[0]), "r"(b[1]));
}

// ---------------------------------------------------------------------------
// Split-precision conversion kernels
// ---------------------------------------------------------------------------
__global__ __launch_bounds__(256) void convert_x_kernel(const float* __restrict__ x) {
    size_t i = ((size_t)blockIdx.x * 256 + threadIdx.x) * 4;
    float4 v = *(const float4*)(x + i);
    __nv_bfloat16 hx = __float2bfloat16(v.x);
    __nv_bfloat16 hy = __float2bfloat16(v.y);
    __nv_bfloat16 hz = __float2bfloat16(v.z);
    __nv_bfloat16 hw = __float2bfloat16(v.w);
    __nv_bfloat16 lx = __float2bfloat16(v.x - __bfloat162float(hx));
    __nv_bfloat16 ly = __float2bfloat16(v.y - __bfloat162float(hy));
    __nv_bfloat16 lz = __float2bfloat16(v.z - __bfloat162float(hz));
    __nv_bfloat16 lw = __float2bfloat16(v.w - __bfloat162float(hw));
    __nv_bfloat162* ph = (__nv_bfloat162*)(g_xhi + i);
    __nv_bfloat162* pl = (__nv_bfloat162*)(g_xlo + i);
    ph[0] = __nv_bfloat162(hx, hy); ph[1] = __nv_bfloat162(hz, hw);
    pl[0] = __nv_bfloat162(lx, ly); pl[1] = __nv_bfloat162(lz, lw);
}

// W row n' = h*4 + g (gate-interleaved N), col k.
__global__ __launch_bounds__(256) void convert_w_kernel(
    const float* __restrict__ Wf, const float* __restrict__ Wi,
    const float* __restrict__ Wo, const float* __restrict__ Wc)
{
    int idx = blockIdx.x * 256 + threadIdx.x;       // [n'][k], 0 .. 4*512*512-1
    int np = idx >> 9;                              // 0..2047
    int k  = idx & 511;
    int h  = np >> 2;
    int g  = np & 3;
    const float* W = (g == 0) ? Wf : (g == 1) ? Wi : (g == 2) ? Wo : Wc;
    float v = W[k * HH + h];                        // transpose: [k][h] -> [n'][k]
    __nv_bfloat16 hh = __float2bfloat16(v);
    g_wth[idx] = hh;
    g_wtl[idx] = __float2bfloat16(v - __bfloat162float(hh));
}

// ---------------------------------------------------------------------------
// mma.sync GEMM: M=65536, N=2048 (gate-interleaved), K=512.
// CTA: 128x128, BK=64, 8 warps (2x4), warp tile 64x32, fp32 reg accum.
// D = x_hi*W_hi + x_hi*W_lo + x_lo*W_hi
// grid = (16 n-tiles, 512 m-tiles)
// ---------------------------------------------------------------------------
#define BKC     64
#define NKCH    (II / BKC)           // 8 chunks
#define TILE_B  16384                // bytes per operand tile (128 x 128B)
#define STAGE_B (4 * TILE_B)         // 64KB
#define AH_OFF  0
#define AL_OFF  TILE_B
#define BH_OFF  (2 * TILE_B)
#define BL_OFF  (3 * TILE_B)

__global__ __launch_bounds__(256, 1) void gemm_mma_kernel() {
    extern __shared__ char smem[];
    const uint32_t sb = smem_u32(smem);
    const int tid  = threadIdx.x;
    const int lane = tid & 31;
    const int warp = tid >> 5;
    const int wm = warp >> 2;           // 0..1 -> M offset wm*64
    const int wn = warp & 3;            // 0..3 -> N offset wn*32

    const int nt = blockIdx.x;          // 0..15
    const int my = blockIdx.y;          // 0..511

    const __nv_bfloat16* __restrict__ Ahg = g_xhi + (size_t)my * 128 * II;
    const __nv_bfloat16* __restrict__ Alg = g_xlo + (size_t)my * 128 * II;
    const __nv_bfloat16* __restrict__ Bhg = g_wth + (size_t)nt * 128 * II;
    const __nv_bfloat16* __restrict__ Blg = g_wtl + (size_t)nt * 128 * II;

    auto load_chunk = [&](int c, int s) {
        const uint32_t stg = sb + (uint32_t)s * STAGE_B;
        const int ko = c * BKC;
        #pragma unroll
        for (int i = 0; i < 4; i++) {
            const int u   = tid + i * 256;          // 0..1023
            const int row = u >> 3;
            const int un  = u & 7;
            const uint32_t so = SWZ128((uint32_t)(row * 128 + un * 16));
            const size_t  go = (size_t)row * II + ko + un * 8;
            cp_async16(stg + AH_OFF + so, Ahg + go);
            cp_async16(stg + AL_OFF + so, Alg + go);
            cp_async16(stg + BH_OFF + so, Bhg + go);
            cp_async16(stg + BL_OFF + so, Blg + go);
        }
        CP_COMMIT();
    };

    float acc[4][4][4];
    #pragma unroll
    for (int mi = 0; mi < 4; mi++)
        #pragma unroll
        for (int ni = 0; ni < 4; ni++)
            #pragma unroll
            for (int r = 0; r < 4; r++) acc[mi][ni][r] = 0.0f;

    const int arow = (lane & 15);                   // fragment row
    const int akseg = (lane >> 4) << 4;             // 0 or 16 bytes
    const int brow = (lane & 7);
    const int bkseg = ((lane >> 3) & 1) << 4;

    load_chunk(0, 0);

    for (int c = 0; c < NKCH; c++) {
        const int s = c & 1;
        if (c + 1 < NKCH) { load_chunk(c + 1, (c + 1) & 1); CP_WAIT(1); }
        else              { CP_WAIT(0); }
        __syncthreads();

        const uint32_t stg = sb + (uint32_t)s * STAGE_B;
        #pragma unroll
        for (int kk = 0; kk < 4; kk++) {
            const int kb = kk * 32;                 // byte offset of 16-k group
            uint32_t ah[4][4], al[4][4], bh[4][2], bl[4][2];
            #pragma unroll
            for (int mi = 0; mi < 4; mi++) {
                const int r = wm * 64 + mi * 16 + arow;
                const uint32_t off = SWZ128((uint32_t)(r * 128 + kb + akseg));
                ldmatrix_x4(ah[mi][0], ah[mi][1], ah[mi][2], ah[mi][3],
                            stg + AH_OFF + off);
                ldmatrix_x4(al[mi][0], al[mi][1], al[mi][2], al[mi][3],
                            stg + AL_OFF + off);
            }
            #pragma unroll
            for (int ni = 0; ni < 4; ni++) {
                const int r = wn * 32 + ni * 8 + brow;
                const uint32_t off = SWZ128((uint32_t)(r * 128 + kb + bkseg));
                ldmatrix_x2(bh[ni][0], bh[ni][1], stg + BH_OFF + off);
                ldmatrix_x2(bl[ni][0], bl[ni][1], stg + BL_OFF + off);
            }
            #pragma unroll
            for (int mi = 0; mi < 4; mi++)
                #pragma unroll
                for (int ni = 0; ni < 4; ni++) {
                    mma_bf16(acc[mi][ni], ah[mi], bh[ni]);
                    mma_bf16(acc[mi][ni], ah[mi], bl[ni]);
                    mma_bf16(acc[mi][ni], al[mi], bh[ni]);
                }
        }
        __syncthreads();
    }

    // ---- epilogue: direct stores into gate-interleaved time-major layout.
    // m = my*128 + r -> b_ = my>>4, t = (my&15)*128 + r
    // n (global, gate-interleaved) = nt*128 + cl; addr = (t*BH + b_*HH)*4 + n
    const int b_ = my >> 4;
    const int t0 = (my & 15) << 7;
    float* plane = g_pre + ((size_t)t0 * BH + (size_t)b_ * HH) * 4 + nt * 128;
    const size_t rstride = (size_t)BH * 4;

    #pragma unroll
    for (int mi = 0; mi < 4; mi++) {
        const int r0 = wm * 64 + mi * 16 + (lane >> 2);
        #pragma unroll
        for (int ni = 0; ni < 4; ni++) {
            const int cl = wn * 32 + ni * 8 + (lane & 3) * 2;
            float* p0 = plane + (size_t)r0 * rstride + cl;
            float* p1 = p0 + 8 * rstride;
            *(float2*)p0 = make_float2(acc[mi][ni][0], acc[mi][ni][1]);
            *(float2*)p1 = make_float2(acc[mi][ni][2], acc[mi][ni][3]);
        }
    }
}

// ---------------------------------------------------------------------------
// Scan: one thread per (b,h). Gate-interleaved pre -> one float4 per step.
// 8-step register double buffer fed by un-sinkable asm volatile v4 loads.
// ---------------------------------------------------------------------------
__device__ __forceinline__ float frcp(float x) {
    float y;
    asm("rcp.approx.f32 %0, %1;" : "=f"(y) : "f"(x));
    return y;
}
__device__ __forceinline__ float sigf(float x) {
    return frcp(1.0f + __expf(-x));
}
__device__ __forceinline__ float ftanh(float x) {
    return __fmaf_rn(2.0f, sigf(2.0f * x), -1.0f);
}

__device__ __forceinline__ void ldg_v4(float4& v, const float* p) {
    asm volatile("ld.global.cg.v4.f32 {%0,%1,%2,%3}, [%4];"
                 : "=f"(v.x), "=f"(v.y), "=f"(v.z), "=f"(v.w) : "l"(p));
}

#define SCAN_THREADS 64
#define SDEPTH 8

__global__ __launch_bounds__(SCAN_THREADS, 1) void scan_kernel(
    const float* __restrict__ u_f, const float* __restrict__ b_f,
    const float* __restrict__ u_i, const float* __restrict__ b_i,
    const float* __restrict__ u_o, const float* __restrict__ b_o,
    const float* __restrict__ u_c, const float* __restrict__ b_c,
    float* __restrict__ out)
{
    const int idx = blockIdx.x * SCAN_THREADS + threadIdx.x;   // 0..BH-1
    const int b = idx >> 9;
    const int h = idx & 511;

    const float uf = u_f[h], bf = b_f[h];
    const float ui = u_i[h], bi = b_i[h];
    const float uo = u_o[h], bo = b_o[h];
    const float uc = u_c[h], bc = b_c[h];

    const float* __restrict__ pp = g_pre + (size_t)idx * 4;    // step stride BH*4
    const size_t tstride = (size_t)BH * 4;
    float* __restrict__ ho = out + (size_t)b * TT * HH + h;

    float4 cur[SDEPTH], nxt[SDEPTH];
    #pragma unroll
    for (int j = 0; j < SDEPTH; j++) ldg_v4(cur[j], pp + (size_t)j * tstride);

    float hv = 0.0f, cv = 0.0f;
    for (int tb = 0; tb < TT; tb += SDEPTH) {
        const int tn = tb + SDEPTH;
        if (tn < TT) {
            #pragma unroll
            for (int j = 0; j < SDEPTH; j++)
                ldg_v4(nxt[j], pp + (size_t)(tn + j) * tstride);
        }
        #pragma unroll
        for (int j = 0; j < SDEPTH; j++) {
            const float gf = cur[j].x + fmaf(hv, uf, bf);
            const float gi = cur[j].y + fmaf(hv, ui, bi);
            const float go = cur[j].z + fmaf(hv, uo, bo);
            const float gc = cur[j].w + fmaf(hv, uc, bc);
            cv = fmaf(sigf(gf), cv, sigf(gi) * ftanh(gc));
            hv = sigf(go) * ftanh(cv);
            ho[(size_t)(tb + j) * HH] = hv;
        }
        #pragma unroll
        for (int j = 0; j < SDEPTH; j++) cur[j] = nxt[j];
    }

    // h_t / c_t tails are zeros
    out[(size_t)BB * TT * HH + idx]      = 0.0f;
    out[(size_t)BB * TT * HH + BH + idx] = 0.0f;
}

// ---------------------------------------------------------------------------
// Launch
// ---------------------------------------------------------------------------
extern "C" void kernel_launch(void* const* d_in, const int* in_sizes, int n_in,
                              void* d_out, int out_size)
{
    const float* x   = (const float*)d_in[0];
    const float* W_f = (const float*)d_in[1];
    const float* u_f = (const float*)d_in[2];
    const float* b_f = (const float*)d_in[3];
    const float* W_i = (const float*)d_in[4];
    const float* u_i = (const float*)d_in[5];
    const float* b_i = (const float*)d_in[6];
    const float* W_o = (const float*)d_in[7];
    const float* u_o = (const float*)d_in[8];
    const float* b_o = (const float*)d_in[9];
    const float* W_c = (const float*)d_in[10];
    const float* u_c = (const float*)d_in[11];
    const float* b_c = (const float*)d_in[12];
    float* out = (float*)d_out;

    static int smem_set = 0;
    if (!smem_set) {
        cudaFuncSetAttribute(gemm_mma_kernel,
                             cudaFuncAttributeMaxDynamicSharedMemorySize,
                             2 * STAGE_B);
        smem_set = 1;
    }

    convert_x_kernel<<<(int)((size_t)MM * II / (256 * 4)), 256>>>(x);
    convert_w_kernel<<<4 * II * HH / 256, 256>>>(W_f, W_i, W_o, W_c);

    dim3 ggrid(16, 512);
    gemm_mma_kernel<<<ggrid, 256, 2 * STAGE_B>>>();

    scan_kernel<<<BH / SCAN_THREADS, SCAN_THREADS>>>(u_f, b_f, u_i, b_i,
                                                     u_o, b_o, u_c, b_c, out);
}

// round 14
// speedup vs baseline: 4.1878x; 1.2417x over previous
#include <cuda_runtime.h>
#include <cuda_fp16.h>
#include <cstdint>
#include <cstddef>

// ---------------------------------------------------------------------------
// Problem constants
// ---------------------------------------------------------------------------
#define BB 32
#define TT 2048
#define II 512
#define HH 512
#define MM (BB * TT)                 // 65536 GEMM rows
#define BH (BB * HH)                 // 16384
#define GSZ ((size_t)TT * BH)        // elems per gate plane

// Scratch (device globals; no runtime allocation allowed)
// g_pre layout: [t][b*H + h][4 gates]  (gate-interleaved, 512 MB)
__device__ float   g_pre[4ull * GSZ];
__device__ __half  g_x16[(size_t)MM * II];      // 64 MB, single fp16 plane
// W transposed + gate-interleaved 2-part fp16: row n' = h*4 + g, col k. [2048][512]
__device__ __half  g_wth[4ull * HH * II];
__device__ __half  g_wtl[4ull * HH * II];

// ---------------------------------------------------------------------------
// Helpers (base-ISA only: cp.async / ldmatrix / mma.sync all work at sm_103)
// ---------------------------------------------------------------------------
__device__ __forceinline__ uint32_t smem_u32(const void* p) {
    uint32_t a;
    asm("{ .reg .u64 t; cvta.to.shared.u64 t, %1; cvt.u32.u64 %0, t; }"
        : "=r"(a) : "l"(p));
    return a;
}

#define SWZ128(off) ((off) ^ (((off) >> 3) & 0x70))

__device__ __forceinline__ void cp_async16(uint32_t saddr, const void* gaddr) {
    asm volatile("cp.async.cg.shared.global [%0], [%1], 16;"
                 :: "r"(saddr), "l"(gaddr));
}
#define CP_COMMIT() asm volatile("cp.async.commit_group;" ::: "memory")
#define CP_WAIT(n)  asm volatile("cp.async.wait_group %0;" :: "n"(n) : "memory")

__device__ __forceinline__ void ldmatrix_x4(uint32_t& r0, uint32_t& r1,
                                            uint32_t& r2, uint32_t& r3,
                                            uint32_t addr) {
    asm volatile("ldmatrix.sync.aligned.m8n8.x4.shared.b16 {%0,%1,%2,%3}, [%4];"
                 : "=r"(r0), "=r"(r1), "=r"(r2), "=r"(r3) : "r"(addr));
}
__device__ __forceinline__ void ldmatrix_x2(uint32_t& r0, uint32_t& r1,
                                            uint32_t addr) {
    asm volatile("ldmatrix.sync.aligned.m8n8.x2.shared.b16 {%0,%1}, [%2];"
                 : "=r"(r0), "=r"(r1) : "r"(addr));
}

__device__ __forceinline__ void mma_f16(float* c, const uint32_t* a,
                                        const uint32_t* b) {
    asm volatile(
        "mma.sync.aligned.m16n8k16.row.col.f32.f16.f16.f32 "
        "{%0,%1,%2,%3}, {%4,%5,%6,%7}, {%8,%9}, {%0,%1,%2,%3};"
        : "+f"(c[0]), "+f"(c[1]), "+f"(c[2]), "+f"(c[3])
        : "r"(a[0]), "r"(a[1]), "r"(a[2]), "r"(a[3]), "r"(b[0]), "r"(b[1]));
}

// ---------------------------------------------------------------------------
// Conversion kernels
// ---------------------------------------------------------------------------
__global__ __launch_bounds__(256) void convert_x_kernel(const float* __restrict__ x) {
    size_t i = ((size_t)blockIdx.x * 256 + threadIdx.x) * 4;
    float4 v = *(const float4*)(x + i);
    __half2* p = (__half2*)(g_x16 + i);
    p[0] = __half2(__float2half(v.x), __float2half(v.y));
    p[1] = __half2(__float2half(v.z), __float2half(v.w));
}

// W 2-part fp16, row n' = h*4 + g (gate-interleaved N), col k.
__global__ __launch_bounds__(256) void convert_w_kernel(
    const float* __restrict__ Wf, const float* __restrict__ Wi,
    const float* __restrict__ Wo, const float* __restrict__ Wc)
{
    int idx = blockIdx.x * 256 + threadIdx.x;       // [n'][k], 0 .. 4*512*512-1
    int np = idx >> 9;                              // 0..2047
    int k  = idx & 511;
    int h  = np >> 2;
    int g  = np & 3;
    const float* W = (g == 0) ? Wf : (g == 1) ? Wi : (g == 2) ? Wo : Wc;
    float v = W[k * HH + h];                        // transpose: [k][h] -> [n'][k]
    __half hi = __float2half(v);
    g_wth[idx] = hi;
    g_wtl[idx] = __float2half(v - __half2float(hi));
}

// ---------------------------------------------------------------------------
// mma.sync GEMM: M=65536, N=2048 (gate-interleaved), K=512.
// CTA: 128x128, BK=64, 8 warps (2x4), warp tile 64x32, fp32 reg accum.
// D = x16*W_hi + x16*W_lo   (fp16 inputs, fp32 accumulate)
// smem per stage: A(16K) Bh(16K) Bl(16K) = 48KB; 2 stages = 96KB.
// grid = (16 n-tiles, 512 m-tiles)
// ---------------------------------------------------------------------------
#define BKC     64
#define NKCH    (II / BKC)           // 8 chunks
#define TILE_B  16384                // bytes per operand tile (128 x 128B)
#define STAGE_B (3 * TILE_B)         // 48KB
#define A_OFF   0
#define BH_OFF  TILE_B
#define BL_OFF  (2 * TILE_B)

__global__ __launch_bounds__(256, 1) void gemm_mma_kernel() {
    extern __shared__ char smem[];
    const uint32_t sb = smem_u32(smem);
    const int tid  = threadIdx.x;
    const int lane = tid & 31;
    const int warp = tid >> 5;
    const int wm = warp >> 2;           // 0..1 -> M offset wm*64
    const int wn = warp & 3;            // 0..3 -> N offset wn*32

    const int nt = blockIdx.x;          // 0..15
    const int my = blockIdx.y;          // 0..511

    const __half* __restrict__ Ag  = g_x16 + (size_t)my * 128 * II;
    const __half* __restrict__ Bhg = g_wth + (size_t)nt * 128 * II;
    const __half* __restrict__ Blg = g_wtl + (size_t)nt * 128 * II;

    auto load_chunk = [&](int c, int s) {
        const uint32_t stg = sb + (uint32_t)s * STAGE_B;
        const int ko = c * BKC;
        #pragma unroll
        for (int i = 0; i < 4; i++) {
            const int u   = tid + i * 256;          // 0..1023
            const int row = u >> 3;
            const int un  = u & 7;
            const uint32_t so = SWZ128((uint32_t)(row * 128 + un * 16));
            const size_t  go = (size_t)row * II + ko + un * 8;
            cp_async16(stg + A_OFF  + so, Ag  + go);
            cp_async16(stg + BH_OFF + so, Bhg + go);
            cp_async16(stg + BL_OFF + so, Blg + go);
        }
        CP_COMMIT();
    };

    float acc[4][4][4];
    #pragma unroll
    for (int mi = 0; mi < 4; mi++)
        #pragma unroll
        for (int ni = 0; ni < 4; ni++)
            #pragma unroll
            for (int r = 0; r < 4; r++) acc[mi][ni][r] = 0.0f;

    const int arow = (lane & 15);                   // fragment row
    const int akseg = (lane >> 4) << 4;             // 0 or 16 bytes
    const int brow = (lane & 7);
    const int bkseg = ((lane >> 3) & 1) << 4;

    load_chunk(0, 0);

    for (int c = 0; c < NKCH; c++) {
        const int s = c & 1;
        if (c + 1 < NKCH) { load_chunk(c + 1, (c + 1) & 1); CP_WAIT(1); }
        else              { CP_WAIT(0); }
        __syncthreads();

        const uint32_t stg = sb + (uint32_t)s * STAGE_B;
        #pragma unroll
        for (int kk = 0; kk < 4; kk++) {
            const int kb = kk * 32;                 // byte offset of 16-k group
            uint32_t a[4][4], bh[4][2], bl[4][2];
            #pragma unroll
            for (int mi = 0; mi < 4; mi++) {
                const int r = wm * 64 + mi * 16 + arow;
                const uint32_t off = SWZ128((uint32_t)(r * 128 + kb + akseg));
                ldmatrix_x4(a[mi][0], a[mi][1], a[mi][2], a[mi][3],
                            stg + A_OFF + off);
            }
            #pragma unroll
            for (int ni = 0; ni < 4; ni++) {
                const int r = wn * 32 + ni * 8 + brow;
                const uint32_t off = SWZ128((uint32_t)(r * 128 + kb + bkseg));
                ldmatrix_x2(bh[ni][0], bh[ni][1], stg + BH_OFF + off);
                ldmatrix_x2(bl[ni][0], bl[ni][1], stg + BL_OFF + off);
            }
            #pragma unroll
            for (int mi = 0; mi < 4; mi++)
                #pragma unroll
                for (int ni = 0; ni < 4; ni++) {
                    mma_f16(acc[mi][ni], a[mi], bh[ni]);
                    mma_f16(acc[mi][ni], a[mi], bl[ni]);
                }
        }
        __syncthreads();
    }

    // ---- epilogue: direct stores into gate-interleaved time-major layout.
    // m = my*128 + r -> b_ = my>>4, t = (my&15)*128 + r
    // n (global, gate-interleaved) = nt*128 + cl; addr = (t*BH + b_*HH)*4 + n
    const int b_ = my >> 4;
    const int t0 = (my & 15) << 7;
    float* plane = g_pre + ((size_t)t0 * BH + (size_t)b_ * HH) * 4 + nt * 128;
    const size_t rstride = (size_t)BH * 4;

    #pragma unroll
    for (int mi = 0; mi < 4; mi++) {
        const int r0 = wm * 64 + mi * 16 + (lane >> 2);
        #pragma unroll
        for (int ni = 0; ni < 4; ni++) {
            const int cl = wn * 32 + ni * 8 + (lane & 3) * 2;
            float* p0 = plane + (size_t)r0 * rstride + cl;
            float* p1 = p0 + 8 * rstride;
            *(float2*)p0 = make_float2(acc[mi][ni][0], acc[mi][ni][1]);
            *(float2*)p1 = make_float2(acc[mi][ni][2], acc[mi][ni][3]);
        }
    }
}

// ---------------------------------------------------------------------------
// Scan: one thread per (b,h). Gate-interleaved pre -> one float4 per step.
// 8-step register double buffer fed by un-sinkable asm volatile v4 loads.
// ---------------------------------------------------------------------------
__device__ __forceinline__ float frcp(float x) {
    float y;
    asm("rcp.approx.f32 %0, %1;" : "=f"(y) : "f"(x));
    return y;
}
__device__ __forceinline__ float sigf(float x) {
    return frcp(1.0f + __expf(-x));
}
__device__ __forceinline__ float ftanh(float x) {
    return __fmaf_rn(2.0f, sigf(2.0f * x), -1.0f);
}

__device__ __forceinline__ void ldg_v4(float4& v, const float* p) {
    asm volatile("ld.global.cg.v4.f32 {%0,%1,%2,%3}, [%4];"
                 : "=f"(v.x), "=f"(v.y), "=f"(v.z), "=f"(v.w) : "l"(p));
}

#define SCAN_THREADS 64
#define SDEPTH 8

__global__ __launch_bounds__(SCAN_THREADS, 1) void scan_kernel(
    const float* __restrict__ u_f, const float* __restrict__ b_f,
    const float* __restrict__ u_i, const float* __restrict__ b_i,
    const float* __restrict__ u_o, const float* __restrict__ b_o,
    const float* __restrict__ u_c, const float* __restrict__ b_c,
    float* __restrict__ out)
{
    const int idx = blockIdx.x * SCAN_THREADS + threadIdx.x;   // 0..BH-1
    const int b = idx >> 9;
    const int h = idx & 511;

    const float uf = u_f[h], bf = b_f[h];
    const float ui = u_i[h], bi = b_i[h];
    const float uo = u_o[h], bo = b_o[h];
    const float uc = u_c[h], bc = b_c[h];

    const float* __restrict__ pp = g_pre + (size_t)idx * 4;    // step stride BH*4
    const size_t tstride = (size_t)BH * 4;
    float* __restrict__ ho = out + (size_t)b * TT * HH + h;

    float4 cur[SDEPTH], nxt[SDEPTH];
    #pragma unroll
    for (int j = 0; j < SDEPTH; j++) ldg_v4(cur[j], pp + (size_t)j * tstride);

    float hv = 0.0f, cv = 0.0f;
    for (int tb = 0; tb < TT; tb += SDEPTH) {
        const int tn = tb + SDEPTH;
        if (tn < TT) {
            #pragma unroll
            for (int j = 0; j < SDEPTH; j++)
                ldg_v4(nxt[j], pp + (size_t)(tn + j) * tstride);
        }
        #pragma unroll
        for (int j = 0; j < SDEPTH; j++) {
            const float gf = cur[j].x + fmaf(hv, uf, bf);
            const float gi = cur[j].y + fmaf(hv, ui, bi);
            const float go = cur[j].z + fmaf(hv, uo, bo);
            const float gc = cur[j].w + fmaf(hv, uc, bc);
            cv = fmaf(sigf(gf), cv, sigf(gi) * ftanh(gc));
            hv = sigf(go) * ftanh(cv);
            ho[(size_t)(tb + j) * HH] = hv;
        }
        #pragma unroll
        for (int j = 0; j < SDEPTH; j++) cur[j] = nxt[j];
    }

    // h_t / c_t tails are zeros
    out[(size_t)BB * TT * HH + idx]      = 0.0f;
    out[(size_t)BB * TT * HH + BH + idx] = 0.0f;
}

// ---------------------------------------------------------------------------
// Launch
// ---------------------------------------------------------------------------
extern "C" void kernel_launch(void* const* d_in, const int* in_sizes, int n_in,
                              void* d_out, int out_size)
{
    const float* x   = (const float*)d_in[0];
    const float* W_f = (const float*)d_in[1];
    const float* u_f = (const float*)d_in[2];
    const float* b_f = (const float*)d_in[3];
    const float* W_i = (const float*)d_in[4];
    const float* u_i = (const float*)d_in[5];
    const float* b_i = (const float*)d_in[6];
    const float* W_o = (const float*)d_in[7];
    const float* u_o = (const float*)d_in[8];
    const float* b_o = (const float*)d_in[9];
    const float* W_c = (const float*)d_in[10];
    const float* u_c = (const float*)d_in[11];
    const float* b_c = (const float*)d_in[12];
    float* out = (float*)d_out;

    static int smem_set = 0;
    if (!smem_set) {
        cudaFuncSetAttribute(gemm_mma_kernel,
                             cudaFuncAttributeMaxDynamicSharedMemorySize,
                             2 * STAGE_B);
        smem_set = 1;
    }

    convert_x_kernel<<<(int)((size_t)MM * II / (256 * 4)), 256>>>(x);
    convert_w_kernel<<<4 * II * HH / 256, 256>>>(W_f, W_i, W_o, W_c);

    dim3 ggrid(16, 512);
    gemm_mma_kernel<<<ggrid, 256, 2 * STAGE_B>>>();

    scan_kernel<<<BH / SCAN_THREADS, SCAN_THREADS>>>(u_f, b_f, u_i, b_i,
                                                     u_o, b_o, u_c, b_c, out);
}

// round 15
// speedup vs baseline: 4.5247x; 1.0804x over previous
#include <cuda_runtime.h>
#include <cuda_fp16.h>
#include <cstdint>
#include <cstddef>

// ---------------------------------------------------------------------------
// Problem constants
// ---------------------------------------------------------------------------
#define BB 32
#define TT 2048
#define II 512
#define HH 512
#define MM (BB * TT)                 // 65536 GEMM rows
#define BH (BB * HH)                 // 16384
#define GSZ ((size_t)TT * BH)        // elems per gate plane

// Scratch (device globals; no runtime allocation allowed)
// g_pre layout: [t][b*H + h][4 gates]  (gate-interleaved, 512 MB)
__device__ float   g_pre[4ull * GSZ];
__device__ __half  g_x16[(size_t)MM * II];      // 64 MB, single fp16 plane
// W transposed + gate-interleaved 2-part fp16: row n' = h*4 + g, col k. [2048][512]
__device__ __half  g_wth[4ull * HH * II];
__device__ __half  g_wtl[4ull * HH * II];

// ---------------------------------------------------------------------------
// Helpers (base-ISA only: cp.async / ldmatrix / mma.sync all work at sm_103)
// ---------------------------------------------------------------------------
__device__ __forceinline__ uint32_t smem_u32(const void* p) {
    uint32_t a;
    asm("{ .reg .u64 t; cvta.to.shared.u64 t, %1; cvt.u32.u64 %0, t; }"
        : "=r"(a) : "l"(p));
    return a;
}

#define SWZ128(off) ((off) ^ (((off) >> 3) & 0x70))

__device__ __forceinline__ void cp_async16(uint32_t saddr, const void* gaddr) {
    asm volatile("cp.async.cg.shared.global [%0], [%1], 16;"
                 :: "r"(saddr), "l"(gaddr));
}
#define CP_COMMIT() asm volatile("cp.async.commit_group;" ::: "memory")
#define CP_WAIT(n)  asm volatile("cp.async.wait_group %0;" :: "n"(n) : "memory")

__device__ __forceinline__ void ldmatrix_x4(uint32_t& r0, uint32_t& r1,
                                            uint32_t& r2, uint32_t& r3,
                                            uint32_t addr) {
    asm volatile("ldmatrix.sync.aligned.m8n8.x4.shared.b16 {%0,%1,%2,%3}, [%4];"
                 : "=r"(r0), "=r"(r1), "=r"(r2), "=r"(r3) : "r"(addr));
}
__device__ __forceinline__ void ldmatrix_x2(uint32_t& r0, uint32_t& r1,
                                            uint32_t addr) {
    asm volatile("ldmatrix.sync.aligned.m8n8.x2.shared.b16 {%0,%1}, [%2];"
                 : "=r"(r0), "=r"(r1) : "r"(addr));
}

__device__ __forceinline__ void mma_f16(float* c, const uint32_t* a,
                                        const uint32_t* b) {
    asm volatile(
        "mma.sync.aligned.m16n8k16.row.col.f32.f16.f16.f32 "
        "{%0,%1,%2,%3}, {%4,%5,%6,%7}, {%8,%9}, {%0,%1,%2,%3};"
        : "+f"(c[0]), "+f"(c[1]), "+f"(c[2]), "+f"(c[3])
        : "r"(a[0]), "r"(a[1]), "r"(a[2]), "r"(a[3]), "r"(b[0]), "r"(b[1]));
}

// ---------------------------------------------------------------------------
// Conversion kernels
// ---------------------------------------------------------------------------
__global__ __launch_bounds__(256) void convert_x_kernel(const float* __restrict__ x) {
    size_t i = ((size_t)blockIdx.x * 256 + threadIdx.x) * 4;
    float4 v = *(const float4*)(x + i);
    __half2* p = (__half2*)(g_x16 + i);
    p[0] = __half2(__float2half(v.x), __float2half(v.y));
    p[1] = __half2(__float2half(v.z), __float2half(v.w));
}

// W 2-part fp16, row n' = h*4 + g (gate-interleaved N), col k.
__global__ __launch_bounds__(256) void convert_w_kernel(
    const float* __restrict__ Wf, const float* __restrict__ Wi,
    const float* __restrict__ Wo, const float* __restrict__ Wc)
{
    int idx = blockIdx.x * 256 + threadIdx.x;       // [n'][k], 0 .. 4*512*512-1
    int np = idx >> 9;                              // 0..2047
    int k  = idx & 511;
    int h  = np >> 2;
    int g  = np & 3;
    const float* W = (g == 0) ? Wf : (g == 1) ? Wi : (g == 2) ? Wo : Wc;
    float v = W[k * HH + h];                        // transpose: [k][h] -> [n'][k]
    __half hi = __float2half(v);
    g_wth[idx] = hi;
    g_wtl[idx] = __float2half(v - __half2float(hi));
}

// ---------------------------------------------------------------------------
// mma.sync GEMM: M=65536, N=2048 (gate-interleaved), K=512.
// CTA: 128x128, BK=64, 8 warps (2x4), warp tile 64x32, fp32 reg accum.
// D = x16*W_hi + x16*W_lo   (fp16 inputs, fp32 accumulate)
// grid = (16 n-tiles, 512 m-tiles)
// ---------------------------------------------------------------------------
#define BKC     64
#define NKCH    (II / BKC)           // 8 chunks
#define TILE_B  16384                // bytes per operand tile (128 x 128B)
#define STAGE_B (3 * TILE_B)         // 48KB
#define A_OFF   0
#define BH_OFF  TILE_B
#define BL_OFF  (2 * TILE_B)

__global__ __launch_bounds__(256, 1) void gemm_mma_kernel() {
    extern __shared__ char smem[];
    const uint32_t sb = smem_u32(smem);
    const int tid  = threadIdx.x;
    const int lane = tid & 31;
    const int warp = tid >> 5;
    const int wm = warp >> 2;           // 0..1 -> M offset wm*64
    const int wn = warp & 3;            // 0..3 -> N offset wn*32

    const int nt = blockIdx.x;          // 0..15
    const int my = blockIdx.y;          // 0..511

    const __half* __restrict__ Ag  = g_x16 + (size_t)my * 128 * II;
    const __half* __restrict__ Bhg = g_wth + (size_t)nt * 128 * II;
    const __half* __restrict__ Blg = g_wtl + (size_t)nt * 128 * II;

    auto load_chunk = [&](int c, int s) {
        const uint32_t stg = sb + (uint32_t)s * STAGE_B;
        const int ko = c * BKC;
        #pragma unroll
        for (int i = 0; i < 4; i++) {
            const int u   = tid + i * 256;          // 0..1023
            const int row = u >> 3;
            const int un  = u & 7;
            const uint32_t so = SWZ128((uint32_t)(row * 128 + un * 16));
            const size_t  go = (size_t)row * II + ko + un * 8;
            cp_async16(stg + A_OFF  + so, Ag  + go);
            cp_async16(stg + BH_OFF + so, Bhg + go);
            cp_async16(stg + BL_OFF + so, Blg + go);
        }
        CP_COMMIT();
    };

    float acc[4][4][4];
    #pragma unroll
    for (int mi = 0; mi < 4; mi++)
        #pragma unroll
        for (int ni = 0; ni < 4; ni++)
            #pragma unroll
            for (int r = 0; r < 4; r++) acc[mi][ni][r] = 0.0f;

    const int arow = (lane & 15);                   // fragment row
    const int akseg = (lane >> 4) << 4;             // 0 or 16 bytes
    const int brow = (lane & 7);
    const int bkseg = ((lane >> 3) & 1) << 4;

    load_chunk(0, 0);

    for (int c = 0; c < NKCH; c++) {
        const int s = c & 1;
        if (c + 1 < NKCH) { load_chunk(c + 1, (c + 1) & 1); CP_WAIT(1); }
        else              { CP_WAIT(0); }
        __syncthreads();

        const uint32_t stg = sb + (uint32_t)s * STAGE_B;
        #pragma unroll
        for (int kk = 0; kk < 4; kk++) {
            const int kb = kk * 32;                 // byte offset of 16-k group
            uint32_t a[4][4], bh[4][2], bl[4][2];
            #pragma unroll
            for (int mi = 0; mi < 4; mi++) {
                const int r = wm * 64 + mi * 16 + arow;
                const uint32_t off = SWZ128((uint32_t)(r * 128 + kb + akseg));
                ldmatrix_x4(a[mi][0], a[mi][1], a[mi][2], a[mi][3],
                            stg + A_OFF + off);
            }
            #pragma unroll
            for (int ni = 0; ni < 4; ni++) {
                const int r = wn * 32 + ni * 8 + brow;
                const uint32_t off = SWZ128((uint32_t)(r * 128 + kb + bkseg));
                ldmatrix_x2(bh[ni][0], bh[ni][1], stg + BH_OFF + off);
                ldmatrix_x2(bl[ni][0], bl[ni][1], stg + BL_OFF + off);
            }
            #pragma unroll
            for (int mi = 0; mi < 4; mi++)
                #pragma unroll
                for (int ni = 0; ni < 4; ni++) {
                    mma_f16(acc[mi][ni], a[mi], bh[ni]);
                    mma_f16(acc[mi][ni], a[mi], bl[ni]);
                }
        }
        __syncthreads();
    }

    // ---- epilogue: direct stores into gate-interleaved time-major layout.
    const int b_ = my >> 4;
    const int t0 = (my & 15) << 7;
    float* plane = g_pre + ((size_t)t0 * BH + (size_t)b_ * HH) * 4 + nt * 128;
    const size_t rstride = (size_t)BH * 4;

    #pragma unroll
    for (int mi = 0; mi < 4; mi++) {
        const int r0 = wm * 64 + mi * 16 + (lane >> 2);
        #pragma unroll
        for (int ni = 0; ni < 4; ni++) {
            const int cl = wn * 32 + ni * 8 + (lane & 3) * 2;
            float* p0 = plane + (size_t)r0 * rstride + cl;
            float* p1 = p0 + 8 * rstride;
            *(float2*)p0 = make_float2(acc[mi][ni][0], acc[mi][ni][1]);
            *(float2*)p1 = make_float2(acc[mi][ni][2], acc[mi][ni][3]);
        }
    }
}

// ---------------------------------------------------------------------------
// Scan: one thread per (b,h). Gate-interleaved pre -> one float4 per step.
// HW tanh.approx (MUFU.TANH) shortens the serial chain to ~60 cyc/step.
// Two-phase ping-pong prefetch removes register copies.
// ---------------------------------------------------------------------------
__device__ __forceinline__ float ftanh(float x) {
    float y;
    asm("tanh.approx.f32 %0, %1;" : "=f"(y) : "f"(x));
    return y;
}
__device__ __forceinline__ float sigf(float x) {
    return __fmaf_rn(0.5f, ftanh(0.5f * x), 0.5f);
}

__device__ __forceinline__ void ldg_v4(float4& v, const float* p) {
    asm volatile("ld.global.cg.v4.f32 {%0,%1,%2,%3}, [%4];"
                 : "=f"(v.x), "=f"(v.y), "=f"(v.z), "=f"(v.w) : "l"(p));
}

#define SCAN_THREADS 64
#define SDEPTH 8

__global__ __launch_bounds__(SCAN_THREADS, 1) void scan_kernel(
    const float* __restrict__ u_f, const float* __restrict__ b_f,
    const float* __restrict__ u_i, const float* __restrict__ b_i,
    const float* __restrict__ u_o, const float* __restrict__ b_o,
    const float* __restrict__ u_c, const float* __restrict__ b_c,
    float* __restrict__ out)
{
    const int idx = blockIdx.x * SCAN_THREADS + threadIdx.x;   // 0..BH-1
    const int b = idx >> 9;
    const int h = idx & 511;

    const float uf = u_f[h], bf = b_f[h];
    const float ui = u_i[h], bi = b_i[h];
    const float uo = u_o[h], bo = b_o[h];
    const float uc = u_c[h], bc = b_c[h];

    const float* __restrict__ pp = g_pre + (size_t)idx * 4;    // step stride BH*4
    const size_t tstride = (size_t)BH * 4;
    float* __restrict__ ho = out + (size_t)b * TT * HH + h;

    float4 bufA[SDEPTH], bufB[SDEPTH];
    #pragma unroll
    for (int j = 0; j < SDEPTH; j++) ldg_v4(bufA[j], pp + (size_t)j * tstride);

    float hv = 0.0f, cv = 0.0f;

    #pragma unroll 1
    for (int tb = 0; tb < TT; tb += 2 * SDEPTH) {
        // phase 1: prefetch tb+8..tb+15 into bufB, compute on bufA
        #pragma unroll
        for (int j = 0; j < SDEPTH; j++)
            ldg_v4(bufB[j], pp + (size_t)(tb + SDEPTH + j) * tstride);
        #pragma unroll
        for (int j = 0; j < SDEPTH; j++) {
            const float gf = bufA[j].x + fmaf(hv, uf, bf);
            const float gi = bufA[j].y + fmaf(hv, ui, bi);
            const float go = bufA[j].z + fmaf(hv, uo, bo);
            const float gc = bufA[j].w + fmaf(hv, uc, bc);
            cv = fmaf(sigf(gf), cv, sigf(gi) * ftanh(gc));
            hv = sigf(go) * ftanh(cv);
            ho[(size_t)(tb + j) * HH] = hv;
        }
        // phase 2: prefetch tb+16..tb+23 into bufA (guarded), compute on bufB
        if (tb + 2 * SDEPTH < TT) {
            #pragma unroll
            for (int j = 0; j < SDEPTH; j++)
                ldg_v4(bufA[j], pp + (size_t)(tb + 2 * SDEPTH + j) * tstride);
        }
        #pragma unroll
        for (int j = 0; j < SDEPTH; j++) {
            const float gf = bufB[j].x + fmaf(hv, uf, bf);
            const float gi = bufB[j].y + fmaf(hv, ui, bi);
            const float go = bufB[j].z + fmaf(hv, uo, bo);
            const float gc = bufB[j].w + fmaf(hv, uc, bc);
            cv = fmaf(sigf(gf), cv, sigf(gi) * ftanh(gc));
            hv = sigf(go) * ftanh(cv);
            ho[(size_t)(tb + SDEPTH + j) * HH] = hv;
        }
    }

    // h_t / c_t tails are zeros
    out[(size_t)BB * TT * HH + idx]      = 0.0f;
    out[(size_t)BB * TT * HH + BH + idx] = 0.0f;
}

// ---------------------------------------------------------------------------
// Launch
// ---------------------------------------------------------------------------
extern "C" void kernel_launch(void* const* d_in, const int* in_sizes, int n_in,
                              void* d_out, int out_size)
{
    const float* x   = (const float*)d_in[0];
    const float* W_f = (const float*)d_in[1];
    const float* u_f = (const float*)d_in[2];
    const float* b_f = (const float*)d_in[3];
    const float* W_i = (const float*)d_in[4];
    const float* u_i = (const float*)d_in[5];
    const float* b_i = (const float*)d_in[6];
    const float* W_o = (const float*)d_in[7];
    const float* u_o = (const float*)d_in[8];
    const float* b_o = (const float*)d_in[9];
    const float* W_c = (const float*)d_in[10];
    const float* u_c = (const float*)d_in[11];
    const float* b_c = (const float*)d_in[12];
    float* out = (float*)d_out;

    static int smem_set = 0;
    if (!smem_set) {
        cudaFuncSetAttribute(gemm_mma_kernel,
                             cudaFuncAttributeMaxDynamicSharedMemorySize,
                             2 * STAGE_B);
        smem_set = 1;
    }

    convert_x_kernel<<<(int)((size_t)MM * II / (256 * 4)), 256>>>(x);
    convert_w_kernel<<<4 * II * HH / 256, 256>>>(W_f, W_i, W_o, W_c);

    dim3 ggrid(16, 512);
    gemm_mma_kernel<<<ggrid, 256, 2 * STAGE_B>>>();

    scan_kernel<<<BH / SCAN_THREADS, SCAN_THREADS>>>(u_f, b_f, u_i, b_i,
                                                     u_o, b_o, u_c, b_c, out);
}